// round 4
// baseline (speedup 1.0000x reference)
#include <cuda_runtime.h>
#include <cuda_fp16.h>
#include <cstdint>

#define NTH     512
#define PT      256
#define NPT     39            // PLEN / PT exact
#define NTILES  (128 * NPT)
#define PLEN    9984
#define LL      10000
#define NK      128

// smem layout (bytes); W/V 1024B-aligned
#define XS_OFF  0             // 272 float4 = 4352B
#define W_OFF   5120          // 64KB:  W'[k=128][s=256] fp16, blocked SW128 (rstride 16)
#define V_OFF   70656         // 128KB: V[p=256][s=256] fp16, blocked SW128 (rstride 32)
#define SMEM_TOTAL 201728

static __device__ __forceinline__ uint32_t s2u(const void* p) {
    uint32_t a;
    asm("{ .reg .u64 t; cvta.to.shared.u64 t, %1; cvt.u32.u64 %0, t; }" : "=r"(a) : "l"(p));
    return a;
}

// Blocked SW128 atom layout for [rows x 256 halves] fp16; atom = 8 rows x 128B.
// atom_off = (row>>3) + (s>>6)*rstride, rstride = rows/8.
static __device__ __forceinline__ uint32_t wa(int row, int s, int rstride) {
    uint32_t byte = (uint32_t)((((row >> 3) + (s >> 6) * rstride) << 10) + ((row & 7) << 7) + ((s & 63) << 1));
    return byte ^ ((byte >> 3) & 0x70);
}

static __device__ __forceinline__ uint32_t f2h2(float a, float b) {
    __half2 h = __floats2half2_rn(a, b);
    return *reinterpret_cast<uint32_t*>(&h);
}

static __device__ __forceinline__ void ldsm4(uint32_t (&r)[4], uint32_t addr) {
    asm volatile("ldmatrix.sync.aligned.m8n8.x4.shared.b16 {%0,%1,%2,%3}, [%4];"
        : "=r"(r[0]), "=r"(r[1]), "=r"(r[2]), "=r"(r[3]) : "r"(addr));
}

static __device__ __forceinline__ void mma16816(float (&d)[4], const uint32_t (&a)[4],
                                                uint32_t b0, uint32_t b1) {
    asm volatile("mma.sync.aligned.m16n8k16.row.col.f32.f16.f16.f32 "
        "{%0,%1,%2,%3}, {%4,%5,%6,%7}, {%8,%9}, {%0,%1,%2,%3};"
        : "+f"(d[0]), "+f"(d[1]), "+f"(d[2]), "+f"(d[3])
        : "r"(a[0]), "r"(a[1]), "r"(a[2]), "r"(a[3]), "r"(b0), "r"(b1));
}

__global__ void __launch_bounds__(NTH, 1)
markonv_kernel(const float* __restrict__ x, const float* __restrict__ ker,
               float* __restrict__ out) {
    extern __shared__ char smem[];
    uint32_t sb = s2u(smem);
    const int tid = threadIdx.x;
    const int lane = tid & 31;
    const int wid = tid >> 5;
    const int wm = wid & 3;   // warp M (k): 4 x 32 rows
    const int wn = wid >> 2;  // warp N (p): 4 x 64 cols

    // ---- stage W once per CTA: W'[k][s] = ker[s*128 + k] ----
    for (int idx = tid; idx < 128 * 128; idx += NTH) {
        int k = idx & 127, s = (idx >> 7) << 1;
        *(uint32_t*)(smem + W_OFF + wa(k, s, 16)) =
            f2h2(ker[s * 128 + k], ker[s * 128 + 128 + k]);
    }

    float4* xs4 = (float4*)(smem + XS_OFF);

    // ldmatrix lane addressing (row-within-frag / k-chunk from lane id)
    const int a_row0 = wm * 32 + (lane & 15);
    const int a_schunk = (lane >> 4) << 3;
    const int b_row0 = wn * 64 + (lane & 7) + ((lane >> 4) << 3);
    const int b_schunk = ((lane >> 3) & 1) << 3;

    for (int tile = blockIdx.x; tile < NTILES; tile += gridDim.x) {
        const int b = tile / NPT;
        const int p0 = (tile - b * NPT) * PT;

        // ---- stage x window: 272 positions x 4ch ----
        const float4* xg = (const float4*)(x + ((size_t)b * LL + p0) * 4);
        for (int idx = tid; idx < PT + 16; idx += NTH) xs4[idx] = xg[idx];
        __syncthreads();

        // ---- build V[p][i*16 + c1*4 + c2] = x[p+i][c1]*x[p+i+1][c2] ----
        for (int u = tid; u < PT * 16; u += NTH) {
            const int i = u >> 8, p = u & 255, t = p + i;
            const float4 a = xs4[t], c = xs4[t + 1];
            const int s0 = i << 4;
            char* vb = smem + V_OFF;
            uint4 lo, hi;
            lo.x = f2h2(a.x * c.x, a.x * c.y); lo.y = f2h2(a.x * c.z, a.x * c.w);
            lo.z = f2h2(a.y * c.x, a.y * c.y); lo.w = f2h2(a.y * c.z, a.y * c.w);
            hi.x = f2h2(a.z * c.x, a.z * c.y); hi.y = f2h2(a.z * c.z, a.z * c.w);
            hi.z = f2h2(a.w * c.x, a.w * c.y); hi.w = f2h2(a.w * c.z, a.w * c.w);
            *(uint4*)(vb + wa(p, s0, 32))     = lo;
            *(uint4*)(vb + wa(p, s0 + 8, 32)) = hi;
        }
        __syncthreads();

        // ---- GEMM: D[128k x 256p] = W[128k x 256] * V^T; warp tile 32k x 64p ----
        float acc[2][8][4];
        #pragma unroll
        for (int mf = 0; mf < 2; mf++)
            #pragma unroll
            for (int nf = 0; nf < 8; nf++)
                #pragma unroll
                for (int e = 0; e < 4; e++) acc[mf][nf][e] = 0.f;

        #pragma unroll
        for (int ks = 0; ks < 16; ks++) {
            const int s = ks << 4;
            uint32_t af[2][4];
            ldsm4(af[0], sb + W_OFF + wa(a_row0,      s + a_schunk, 16));
            ldsm4(af[1], sb + W_OFF + wa(a_row0 + 16, s + a_schunk, 16));
            #pragma unroll
            for (int j = 0; j < 4; j++) {
                uint32_t bf[4];
                ldsm4(bf, sb + V_OFF + wa(b_row0 + 16 * j, s + b_schunk, 32));
                mma16816(acc[0][2 * j],     af[0], bf[0], bf[1]);
                mma16816(acc[0][2 * j + 1], af[0], bf[2], bf[3]);
                mma16816(acc[1][2 * j],     af[1], bf[0], bf[1]);
                mma16816(acc[1][2 * j + 1], af[1], bf[2], bf[3]);
            }
        }
        __syncthreads();  // V/XS rewritten next iteration

        // ---- epilogue: direct STG.64, rows = k, cols = consecutive p ----
        {
            const size_t obase = ((size_t)b * NK + wm * 32) * PLEN + p0 + wn * 64;
            const int krow = lane >> 2;
            const int pcol = (lane & 3) * 2;
            #pragma unroll
            for (int mf = 0; mf < 2; mf++) {
                #pragma unroll
                for (int nf = 0; nf < 8; nf++) {
                    size_t o = obase + (size_t)(mf * 16 + krow) * PLEN + nf * 8 + pcol;
                    *(float2*)(out + o)            = make_float2(acc[mf][nf][0], acc[mf][nf][1]);
                    *(float2*)(out + o + 8 * PLEN) = make_float2(acc[mf][nf][2], acc[mf][nf][3]);
                }
            }
        }
    }
}

extern "C" void kernel_launch(void* const* d_in, const int* in_sizes, int n_in,
                              void* d_out, int out_size) {
    static int nsm = 0;
    if (nsm == 0) {
        int dev = 0;
        cudaGetDevice(&dev);
        if (cudaDeviceGetAttribute(&nsm, cudaDevAttrMultiProcessorCount, dev) != cudaSuccess || nsm <= 0)
            nsm = 148;
        cudaFuncSetAttribute(markonv_kernel, cudaFuncAttributeMaxDynamicSharedMemorySize, SMEM_TOTAL);
    }
    markonv_kernel<<<nsm, NTH, SMEM_TOTAL>>>(
        (const float*)d_in[0], (const float*)d_in[1], (float*)d_out);
}

// round 5
// speedup vs baseline: 1.1492x; 1.1492x over previous
#include <cuda_runtime.h>
#include <cuda_fp16.h>
#include <cstdint>

#define NTH     512
#define PT      128
#define NPT     78
#define NTILES  (128 * NPT)
#define PLEN    9984
#define LL      10000
#define NK      128

// smem layout (bytes)
#define XS_OFF  0                 // 2 x 160 float4 = 5120B (144 used per buf)
#define W_OFF   5120              // 64KB: W'[k=128][s=256] fp16, blocked SW128
#define V0_OFF  70656             // 2 x 64KB: V[p=128][s=256] fp16
#define VSZ     65536
#define SMEM_TOTAL 201728

static __device__ __forceinline__ uint32_t s2u(const void* p) {
    uint32_t a;
    asm("{ .reg .u64 t; cvta.to.shared.u64 t, %1; cvt.u32.u64 %0, t; }" : "=r"(a) : "l"(p));
    return a;
}

// Blocked SW128 atom layout for [128 rows x 256 halves]; atom = 8 rows x 128B, rstride 16.
static __device__ __forceinline__ uint32_t wa(int row, int s) {
    uint32_t byte = (uint32_t)((((row >> 3) + ((s >> 6) << 4)) << 10) + ((row & 7) << 7) + ((s & 63) << 1));
    return byte ^ ((byte >> 3) & 0x70);
}

static __device__ __forceinline__ uint32_t f2h2(float a, float b) {
    __half2 h = __floats2half2_rn(a, b);
    return *reinterpret_cast<uint32_t*>(&h);
}

static __device__ __forceinline__ void ldsm4(uint32_t (&r)[4], uint32_t addr) {
    asm volatile("ldmatrix.sync.aligned.m8n8.x4.shared.b16 {%0,%1,%2,%3}, [%4];"
        : "=r"(r[0]), "=r"(r[1]), "=r"(r[2]), "=r"(r[3]) : "r"(addr));
}

static __device__ __forceinline__ void sts128(uint32_t addr, uint4 v) {
    asm volatile("st.shared.v4.b32 [%0], {%1,%2,%3,%4};"
        :: "r"(addr), "r"(v.x), "r"(v.y), "r"(v.z), "r"(v.w));
}

static __device__ __forceinline__ void mma16816(float (&d)[4], const uint32_t (&a)[4],
                                                uint32_t b0, uint32_t b1) {
    asm volatile("mma.sync.aligned.m16n8k16.row.col.f32.f16.f16.f32 "
        "{%0,%1,%2,%3}, {%4,%5,%6,%7}, {%8,%9}, {%0,%1,%2,%3};"
        : "+f"(d[0]), "+f"(d[1]), "+f"(d[2]), "+f"(d[3])
        : "r"(a[0]), "r"(a[1]), "r"(a[2]), "r"(a[3]), "r"(b0), "r"(b1));
}

// one im2col unit: V[p][i*16 + c1*4 + c2] = x[p+i][c1] * x[p+i+1][c2]
static __device__ __forceinline__ void build_u(uint32_t vbase, const float4* xs, int u) {
    const int i = u >> 7, p = u & 127, t = p + i;
    const float4 a = xs[t], c = xs[t + 1];
    const int s0 = i << 4;
    uint4 lo, hi;
    lo.x = f2h2(a.x * c.x, a.x * c.y); lo.y = f2h2(a.x * c.z, a.x * c.w);
    lo.z = f2h2(a.y * c.x, a.y * c.y); lo.w = f2h2(a.y * c.z, a.y * c.w);
    hi.x = f2h2(a.z * c.x, a.z * c.y); hi.y = f2h2(a.z * c.z, a.z * c.w);
    hi.z = f2h2(a.w * c.x, a.w * c.y); hi.w = f2h2(a.w * c.z, a.w * c.w);
    sts128(vbase + wa(p, s0), lo);
    sts128(vbase + wa(p, s0 + 8), hi);
}

static __device__ __forceinline__ float4 ldg_x(const float* x, int tile, int tid) {
    const int b = tile / NPT, p0 = (tile - b * NPT) * PT;
    return ((const float4*)(x + ((size_t)b * LL + p0) * 4))[tid];
}

__global__ void __launch_bounds__(NTH, 1)
markonv_kernel(const float* __restrict__ x, const float* __restrict__ ker,
               float* __restrict__ out) {
    extern __shared__ char smem[];
    uint32_t sb = s2u(smem);
    const int tid = threadIdx.x;
    const int lane = tid & 31;
    const int wid = tid >> 5;
    const int wm = wid & 3;   // warp M (k): 4 x 32 rows
    const int wn = wid >> 2;  // warp N (p): 4 x 32 cols
    const int G = gridDim.x;

    // ---- stage W once: W'[k][s] = ker[s*128 + k] ----
    for (int idx = tid; idx < 128 * 128; idx += NTH) {
        int k = idx & 127, s = (idx >> 7) << 1;
        *(uint32_t*)(smem + W_OFF + wa(k, s)) =
            f2h2(ker[s * 128 + k], ker[s * 128 + 128 + k]);
    }

    const int a_row0 = wm * 32 + (lane & 15);
    const int a_sc   = (lane >> 4) << 3;
    const int b_row0 = wn * 32 + (lane & 7) + ((lane >> 4) << 3);
    const int b_sc   = ((lane >> 3) & 1) << 3;

    int tile = blockIdx.x;
    float4 xr = make_float4(0.f, 0.f, 0.f, 0.f);

    // ---- prologue: stage xs[0], build V[0], prefetch x(tile+G) ----
    if (tid < 144) {
        xr = ldg_x(x, tile, tid);
        ((float4*)(smem + XS_OFF))[tid] = xr;
    }
    __syncthreads();
    {
        const float4* xs0 = (const float4*)(smem + XS_OFF);
        const uint32_t v0 = sb + V0_OFF;
        #pragma unroll
        for (int c = 0; c < 4; c++) build_u(v0, xs0, c * NTH + tid);
    }
    if (tid < 144 && tile + G < NTILES) xr = ldg_x(x, tile + G, tid);

    int n = 0;
    for (; tile < NTILES; tile += G, n++) {
        const int cb = n & 1, nb = cb ^ 1;

        // step 1: publish next x window
        if (tid < 144) ((float4*)(smem + XS_OFF))[nb * 160 + tid] = xr;
        __syncthreads();   // publishes V[cb] (built last iter) and xs[nb]

        const int b = tile / NPT;
        const int p0 = (tile - b * NPT) * PT;

        // step 3: prefetch x(tile+2G) into regs
        if (tid < 144 && tile + 2 * G < NTILES) xr = ldg_x(x, tile + 2 * G, tid);

        // step 4: MMA over V[cb], with build of V[nb] interleaved
        const uint32_t vcur = sb + V0_OFF + cb * VSZ;
        const uint32_t vnxt = sb + V0_OFF + nb * VSZ;
        const float4* xsn = (const float4*)(smem + XS_OFF) + nb * 160;

        float acc[2][4][4];
        #pragma unroll
        for (int mf = 0; mf < 2; mf++)
            #pragma unroll
            for (int nf = 0; nf < 4; nf++)
                #pragma unroll
                for (int e = 0; e < 4; e++) acc[mf][nf][e] = 0.f;

        #pragma unroll
        for (int ks = 0; ks < 16; ks++) {
            const int s = ks << 4;
            uint32_t af[2][4], bf[2][4];
            ldsm4(af[0], sb + W_OFF + wa(a_row0,      s + a_sc));
            ldsm4(af[1], sb + W_OFF + wa(a_row0 + 16, s + a_sc));
            ldsm4(bf[0], vcur + wa(b_row0,      s + b_sc));
            ldsm4(bf[1], vcur + wa(b_row0 + 16, s + b_sc));
            #pragma unroll
            for (int mf = 0; mf < 2; mf++)
                #pragma unroll
                for (int nf = 0; nf < 4; nf++)
                    mma16816(acc[mf][nf], af[mf], bf[nf >> 1][(nf & 1) * 2],
                             bf[nf >> 1][(nf & 1) * 2 + 1]);
            // interleave one im2col chunk of the NEXT tile after ks 2,5,8,11
            if (ks == 2 || ks == 5 || ks == 8 || ks == 11)
                build_u(vnxt, xsn, ((ks - 2) / 3) * NTH + tid);
        }

        // step 5: epilogue, direct STG.64 (rows = k, cols = consecutive p)
        {
            const size_t obase = ((size_t)b * NK + wm * 32) * PLEN + p0 + wn * 32;
            const int krow = lane >> 2;
            const int pcol = (lane & 3) * 2;
            #pragma unroll
            for (int mf = 0; mf < 2; mf++) {
                #pragma unroll
                for (int nf = 0; nf < 4; nf++) {
                    size_t o = obase + (size_t)(mf * 16 + krow) * PLEN + nf * 8 + pcol;
                    *(float2*)(out + o)            = make_float2(acc[mf][nf][0], acc[mf][nf][1]);
                    *(float2*)(out + o + 8 * PLEN) = make_float2(acc[mf][nf][2], acc[mf][nf][3]);
                }
            }
        }
    }
}

extern "C" void kernel_launch(void* const* d_in, const int* in_sizes, int n_in,
                              void* d_out, int out_size) {
    static int nsm = 0;
    if (nsm == 0) {
        int dev = 0;
        cudaGetDevice(&dev);
        if (cudaDeviceGetAttribute(&nsm, cudaDevAttrMultiProcessorCount, dev) != cudaSuccess || nsm <= 0)
            nsm = 148;
        cudaFuncSetAttribute(markonv_kernel, cudaFuncAttributeMaxDynamicSharedMemorySize, SMEM_TOTAL);
    }
    markonv_kernel<<<nsm, NTH, SMEM_TOTAL>>>(
        (const float*)d_in[0], (const float*)d_in[1], (float*)d_out);
}

// round 6
// speedup vs baseline: 1.2709x; 1.1059x over previous
#include <cuda_runtime.h>
#include <cuda_fp16.h>
#include <cstdint>

#define NTH     256
#define PT      128
#define NPT     78
#define NTILES  (128 * NPT)
#define PLEN    9984
#define LL      10000
#define NK      128

// smem layout (bytes)
#define XS_OFF  0                 // 2 x 160 float4 = 5120B (144 used per buf)
#define W_OFF   5120              // 64KB: W'[k=128][s=256] fp16, blocked SW128
#define V0_OFF  70656             // 2 x 64KB: V[p=128][s=256] fp16
#define VSZ     65536
#define SMEM_TOTAL 201728

static __device__ __forceinline__ uint32_t s2u(const void* p) {
    uint32_t a;
    asm("{ .reg .u64 t; cvta.to.shared.u64 t, %1; cvt.u32.u64 %0, t; }" : "=r"(a) : "l"(p));
    return a;
}

// Blocked SW128 atom layout for [128 rows x 256 halves]; atom = 8 rows x 128B, rstride 16.
static __device__ __forceinline__ uint32_t wa(int row, int s) {
    uint32_t byte = (uint32_t)((((row >> 3) + ((s >> 6) << 4)) << 10) + ((row & 7) << 7) + ((s & 63) << 1));
    return byte ^ ((byte >> 3) & 0x70);
}

static __device__ __forceinline__ uint32_t f2h2(float a, float b) {
    __half2 h = __floats2half2_rn(a, b);
    return *reinterpret_cast<uint32_t*>(&h);
}

static __device__ __forceinline__ void ldsm4(uint32_t (&r)[4], uint32_t addr) {
    asm volatile("ldmatrix.sync.aligned.m8n8.x4.shared.b16 {%0,%1,%2,%3}, [%4];"
        : "=r"(r[0]), "=r"(r[1]), "=r"(r[2]), "=r"(r[3]) : "r"(addr));
}

static __device__ __forceinline__ void sts128(uint32_t addr, uint4 v) {
    asm volatile("st.shared.v4.b32 [%0], {%1,%2,%3,%4};"
        :: "r"(addr), "r"(v.x), "r"(v.y), "r"(v.z), "r"(v.w));
}

static __device__ __forceinline__ void mma16816(float (&d)[4], const uint32_t (&a)[4],
                                                uint32_t b0, uint32_t b1) {
    asm volatile("mma.sync.aligned.m16n8k16.row.col.f32.f16.f16.f32 "
        "{%0,%1,%2,%3}, {%4,%5,%6,%7}, {%8,%9}, {%0,%1,%2,%3};"
        : "+f"(d[0]), "+f"(d[1]), "+f"(d[2]), "+f"(d[3])
        : "r"(a[0]), "r"(a[1]), "r"(a[2]), "r"(a[3]), "r"(b0), "r"(b1));
}

// one im2col unit: V[p][i*16 + c1*4 + c2] = x[p+i][c1] * x[p+i+1][c2]
static __device__ __forceinline__ void build_u(uint32_t vbase, const float4* xs, int u) {
    const int i = u >> 7, p = u & 127, t = p + i;
    const float4 a = xs[t], c = xs[t + 1];
    const int s0 = i << 4;
    uint4 lo, hi;
    lo.x = f2h2(a.x * c.x, a.x * c.y); lo.y = f2h2(a.x * c.z, a.x * c.w);
    lo.z = f2h2(a.y * c.x, a.y * c.y); lo.w = f2h2(a.y * c.z, a.y * c.w);
    hi.x = f2h2(a.z * c.x, a.z * c.y); hi.y = f2h2(a.z * c.z, a.z * c.w);
    hi.z = f2h2(a.w * c.x, a.w * c.y); hi.w = f2h2(a.w * c.z, a.w * c.w);
    sts128(vbase + wa(p, s0), lo);
    sts128(vbase + wa(p, s0 + 8), hi);
}

static __device__ __forceinline__ float4 ldg_x(const float* x, int tile, int tid) {
    const int b = tile / NPT, p0 = (tile - b * NPT) * PT;
    return ((const float4*)(x + ((size_t)b * LL + p0) * 4))[tid];
}

__global__ void __launch_bounds__(NTH, 1)
markonv_kernel(const float* __restrict__ x, const float* __restrict__ ker,
               float* __restrict__ out) {
    extern __shared__ char smem[];
    uint32_t sb = s2u(smem);
    const int tid = threadIdx.x;
    const int lane = tid & 31;
    const int wid = tid >> 5;
    const int wm = wid & 1;   // warp M (k): 2 x 64 rows
    const int wn = wid >> 1;  // warp N (p): 4 x 32 cols
    const int G = gridDim.x;

    // ---- stage W once: W'[k][s] = ker[s*128 + k] ----
    for (int idx = tid; idx < 128 * 128; idx += NTH) {
        int k = idx & 127, s = (idx >> 7) << 1;
        *(uint32_t*)(smem + W_OFF + wa(k, s)) =
            f2h2(ker[s * 128 + k], ker[s * 128 + 128 + k]);
    }

    const int a_row0 = wm * 64 + (lane & 15);
    const int a_sc   = (lane >> 4) << 3;
    const int b_row0 = wn * 32 + (lane & 7) + ((lane >> 4) << 3);
    const int b_sc   = ((lane >> 3) & 1) << 3;

    int tile = blockIdx.x;
    float4 xr = make_float4(0.f, 0.f, 0.f, 0.f);

    // ---- prologue: stage xs[0], build V[0], prefetch x(tile+G) ----
    if (tid < 144) {
        xr = ldg_x(x, tile, tid);
        ((float4*)(smem + XS_OFF))[tid] = xr;
    }
    __syncthreads();
    {
        const float4* xs0 = (const float4*)(smem + XS_OFF);
        const uint32_t v0 = sb + V0_OFF;
        #pragma unroll
        for (int c = 0; c < 8; c++) build_u(v0, xs0, c * NTH + tid);
    }
    if (tid < 144 && tile + G < NTILES) xr = ldg_x(x, tile + G, tid);

    int n = 0;
    for (; tile < NTILES; tile += G, n++) {
        const int cb = n & 1, nb = cb ^ 1;

        // publish next x window; barrier publishes V[cb] and xs[nb]
        if (tid < 144) ((float4*)(smem + XS_OFF))[nb * 160 + tid] = xr;
        __syncthreads();

        const int b = tile / NPT;
        const int p0 = (tile - b * NPT) * PT;

        // prefetch x(tile+2G) into regs
        if (tid < 144 && tile + 2 * G < NTILES) xr = ldg_x(x, tile + 2 * G, tid);

        const uint32_t vcur = sb + V0_OFF + cb * VSZ;
        const uint32_t vnxt = sb + V0_OFF + nb * VSZ;
        const float4* xsn = (const float4*)(smem + XS_OFF) + nb * 160;

        float acc[4][4][4];   // [m-frag 16-rows][n-frag 8-cols][elt]
        #pragma unroll
        for (int mf = 0; mf < 4; mf++)
            #pragma unroll
            for (int nf = 0; nf < 4; nf++)
                #pragma unroll
                for (int e = 0; e < 4; e++) acc[mf][nf][e] = 0.f;

        #pragma unroll
        for (int ks = 0; ks < 16; ks++) {
            const int s = ks << 4;
            uint32_t af[4][4], bf[2][4];
            ldsm4(af[0], sb + W_OFF + wa(a_row0,      s + a_sc));
            ldsm4(af[1], sb + W_OFF + wa(a_row0 + 16, s + a_sc));
            ldsm4(af[2], sb + W_OFF + wa(a_row0 + 32, s + a_sc));
            ldsm4(af[3], sb + W_OFF + wa(a_row0 + 48, s + a_sc));
            ldsm4(bf[0], vcur + wa(b_row0,      s + b_sc));
            ldsm4(bf[1], vcur + wa(b_row0 + 16, s + b_sc));
            #pragma unroll
            for (int mf = 0; mf < 4; mf++)
                #pragma unroll
                for (int nf = 0; nf < 4; nf++)
                    mma16816(acc[mf][nf], af[mf], bf[nf >> 1][(nf & 1) * 2],
                             bf[nf >> 1][(nf & 1) * 2 + 1]);
            // interleave one im2col chunk of the NEXT tile after each odd kstep
            if (ks & 1) build_u(vnxt, xsn, (ks >> 1) * NTH + tid);
        }

        // epilogue: direct STG.64 (rows = k, cols = consecutive p)
        {
            const size_t obase = ((size_t)b * NK + wm * 64) * PLEN + p0 + wn * 32;
            const int krow = lane >> 2;
            const int pcol = (lane & 3) * 2;
            #pragma unroll
            for (int mf = 0; mf < 4; mf++) {
                #pragma unroll
                for (int nf = 0; nf < 4; nf++) {
                    size_t o = obase + (size_t)(mf * 16 + krow) * PLEN + nf * 8 + pcol;
                    *(float2*)(out + o)            = make_float2(acc[mf][nf][0], acc[mf][nf][1]);
                    *(float2*)(out + o + 8 * PLEN) = make_float2(acc[mf][nf][2], acc[mf][nf][3]);
                }
            }
        }
    }
}

extern "C" void kernel_launch(void* const* d_in, const int* in_sizes, int n_in,
                              void* d_out, int out_size) {
    static int nsm = 0;
    if (nsm == 0) {
        int dev = 0;
        cudaGetDevice(&dev);
        if (cudaDeviceGetAttribute(&nsm, cudaDevAttrMultiProcessorCount, dev) != cudaSuccess || nsm <= 0)
            nsm = 148;
        cudaFuncSetAttribute(markonv_kernel, cudaFuncAttributeMaxDynamicSharedMemorySize, SMEM_TOTAL);
    }
    markonv_kernel<<<nsm, NTH, SMEM_TOTAL>>>(
        (const float*)d_in[0], (const float*)d_in[1], (float*)d_out);
}

// round 8
// speedup vs baseline: 1.3610x; 1.0709x over previous
#include <cuda_runtime.h>
#include <cuda_fp16.h>
#include <cstdint>

#define NTH     256
#define PT      256
#define NPT     39
#define NTILES  (128 * NPT)
#define PLEN    9984
#define LL      10000
#define NK      128

// smem layout (bytes)
#define XS_OFF  0                 // 2 x 288 float4 (272 used) = 9216B
#define W_OFF   9216              // 64KB: W'[k=128][s=256] fp16, blocked SW128
#define P0_OFF  74752             // 2 x 13056B: P[272 rows][16 cc] fp16, 48B row stride
#define PSZ     13056
#define SMEM_TOTAL 100864

static __device__ __forceinline__ uint32_t s2u(const void* p) {
    uint32_t a;
    asm("{ .reg .u64 t; cvta.to.shared.u64 t, %1; cvt.u32.u64 %0, t; }" : "=r"(a) : "l"(p));
    return a;
}

// Blocked SW128 atom layout for W [128 rows x 256 halves]; atom = 8 rows x 128B, rstride 16.
// Full (store-side) address: swizzle XOR = (row&7)<<4 applied to bits 4-6.
static __device__ __forceinline__ uint32_t wa(int row, int s) {
    uint32_t byte = (uint32_t)((((row >> 3) + ((s >> 6) << 4)) << 10) + ((row & 7) << 7) + ((s & 63) << 1));
    return byte ^ ((byte >> 3) & 0x70);
}
// Unswizzled byte offset (for incremental per-kstep addressing; XOR mask applied after add)
static __device__ __forceinline__ uint32_t wa_u(int row, int s) {
    return (uint32_t)((((row >> 3) + ((s >> 6) << 4)) << 10) + ((row & 7) << 7) + ((s & 63) << 1));
}

static __device__ __forceinline__ uint32_t f2h2(float a, float b) {
    __half2 h = __floats2half2_rn(a, b);
    return *reinterpret_cast<uint32_t*>(&h);
}

static __device__ __forceinline__ void ldsm4(uint32_t (&r)[4], uint32_t addr) {
    asm volatile("ldmatrix.sync.aligned.m8n8.x4.shared.b16 {%0,%1,%2,%3}, [%4];"
        : "=r"(r[0]), "=r"(r[1]), "=r"(r[2]), "=r"(r[3]) : "r"(addr));
}

static __device__ __forceinline__ void sts128(uint32_t addr, uint4 v) {
    asm volatile("st.shared.v4.b32 [%0], {%1,%2,%3,%4};"
        :: "r"(addr), "r"(v.x), "r"(v.y), "r"(v.z), "r"(v.w));
}

static __device__ __forceinline__ void mma16816(float (&d)[4], const uint32_t (&a)[4],
                                                uint32_t b0, uint32_t b1) {
    asm volatile("mma.sync.aligned.m16n8k16.row.col.f32.f16.f16.f32 "
        "{%0,%1,%2,%3}, {%4,%5,%6,%7}, {%8,%9}, {%0,%1,%2,%3};"
        : "+f"(d[0]), "+f"(d[1]), "+f"(d[2]), "+f"(d[3])
        : "r"(a[0]), "r"(a[1]), "r"(a[2]), "r"(a[3]), "r"(b0), "r"(b1));
}

// P row t: P[t][c1*4+c2] = x[t][c1] * x[t+1][c2]; 16 halves = 32B at t*48 (48B stride).
static __device__ __forceinline__ void build_p(uint32_t pbase, const float4* xs, int t) {
    const float4 a = xs[t], c = xs[t + 1];
    uint4 lo, hi;
    lo.x = f2h2(a.x * c.x, a.x * c.y); lo.y = f2h2(a.x * c.z, a.x * c.w);
    lo.z = f2h2(a.y * c.x, a.y * c.y); lo.w = f2h2(a.y * c.z, a.y * c.w);
    hi.x = f2h2(a.z * c.x, a.z * c.y); hi.y = f2h2(a.z * c.z, a.z * c.w);
    hi.z = f2h2(a.w * c.x, a.w * c.y); hi.w = f2h2(a.w * c.z, a.w * c.w);
    sts128(pbase + t * 48, lo);
    sts128(pbase + t * 48 + 16, hi);
}

static __device__ __forceinline__ const float4* xwin(const float* x, int tile) {
    const int b = tile / NPT, p0 = (tile - b * NPT) * PT;
    return (const float4*)(x + ((size_t)b * LL + p0) * 4);
}

__global__ void __launch_bounds__(NTH, 1)
markonv_kernel(const float* __restrict__ x, const float* __restrict__ ker,
               float* __restrict__ out) {
    extern __shared__ char smem[];
    uint32_t sb = s2u(smem);
    const int tid = threadIdx.x;
    const int lane = tid & 31;
    const int wid = tid >> 5;
    const int wm = wid & 1;   // warp M (k): 2 x 64 rows
    const int wn = wid >> 1;  // warp N (p): 4 x 64 cols
    const int G = gridDim.x;

    // ---- stage W once: W'[k][s] = ker[s*128 + k] (full swizzled store addr) ----
    for (int idx = tid; idx < 128 * 128; idx += NTH) {
        int k = idx & 127, s = (idx >> 7) << 1;
        *(uint32_t*)(smem + W_OFF + wa(k, s)) =
            f2h2(ker[s * 128 + k], ker[s * 128 + 128 + k]);
    }

    // A (W) lane addressing: UNSWIZZLED base + per-thread XOR mask (bits 4-6).
    const int a_row = wm * 64 + (lane & 15);
    const uint32_t wbyteU = wa_u(a_row, (lane >> 4) << 3);
    const uint32_t wmask  = (uint32_t)((a_row & 7) << 4);
    // B (P) lane addressing: linear; per-kstep +48, rows +16 -> +768.
    const uint32_t pblane = (uint32_t)((wn * 64 + (lane & 7) + ((lane >> 4) << 3)) * 48
                                       + (((lane >> 3) & 1) << 4));

    int tile = blockIdx.x;
    float4 xr = make_float4(0.f, 0.f, 0.f, 0.f), xrb = xr;

    // ---- prologue: stage xs[0], build P[0], prefetch x(tile+G) ----
    {
        const float4* w0 = xwin(x, tile);
        xr = w0[tid];
        if (tid < 16) xrb = w0[256 + tid];
        float4* xs0 = (float4*)(smem + XS_OFF);
        xs0[tid] = xr;
        if (tid < 16) xs0[256 + tid] = xrb;
        __syncthreads();
        build_p(sb + P0_OFF, xs0, tid);
        if (tid < 16) build_p(sb + P0_OFF, xs0, 256 + tid);
        if (tile + G < NTILES) {
            const float4* w1 = xwin(x, tile + G);
            xr = w1[tid];
            if (tid < 16) xrb = w1[256 + tid];
        }
    }

    int n = 0;
    for (; tile < NTILES; tile += G, n++) {
        const int cb = n & 1, nb = cb ^ 1;

        // publish x window for tile+G; barrier publishes P[cb] and xs[nb]
        float4* xsn = (float4*)(smem + XS_OFF) + nb * 288;
        xsn[tid] = xr;
        if (tid < 16) xsn[256 + tid] = xrb;
        __syncthreads();

        const int b = tile / NPT;
        const int p0 = (tile - b * NPT) * PT;

        // prefetch x(tile+2G)
        if (tile + 2 * G < NTILES) {
            const float4* w2 = xwin(x, tile + 2 * G);
            xr = w2[tid];
            if (tid < 16) xrb = w2[256 + tid];
        }

        // build P[nb] (tiny: 272 rows)
        {
            const uint32_t pn = sb + P0_OFF + nb * PSZ;
            build_p(pn, xsn, tid);
            if (tid < 16) build_p(pn, xsn, 256 + tid);
        }

        // ---- GEMM: D[128k x 256p] = W * V^T, V[p][16ks+cc] = P[p+ks][cc] ----
        const uint32_t pcur = sb + P0_OFF + cb * PSZ + pblane;
        const uint32_t wsb  = sb + W_OFF;

        float acc[4][8][4];
        #pragma unroll
        for (int mf = 0; mf < 4; mf++)
            #pragma unroll
            for (int nf = 0; nf < 8; nf++)
                #pragma unroll
                for (int e = 0; e < 4; e++) acc[mf][nf][e] = 0.f;

        #pragma unroll
        for (int ks = 0; ks < 16; ks++) {
            uint32_t af[4][4], bf[4][4];
            // add kstep delta in UNSWIZZLED space, then XOR the swizzle mask
            const uint32_t ab = wsb + (((wbyteU + (uint32_t)((ks >> 2) * 16384 + (ks & 3) * 32)) ^ wmask));
            const uint32_t bb = pcur + (uint32_t)(ks * 48);
            ldsm4(af[0], ab);
            ldsm4(af[1], ab + 2048);
            ldsm4(af[2], ab + 4096);
            ldsm4(af[3], ab + 6144);
            ldsm4(bf[0], bb);
            ldsm4(bf[1], bb + 768);
            ldsm4(bf[2], bb + 1536);
            ldsm4(bf[3], bb + 2304);
            #pragma unroll
            for (int j = 0; j < 4; j++)
                #pragma unroll
                for (int mf = 0; mf < 4; mf++) {
                    mma16816(acc[mf][2 * j],     af[mf], bf[j][0], bf[j][1]);
                    mma16816(acc[mf][2 * j + 1], af[mf], bf[j][2], bf[j][3]);
                }
        }

        // ---- epilogue: direct STG.64 (rows = k, cols = consecutive p) ----
        {
            const size_t obase = ((size_t)b * NK + wm * 64) * PLEN + p0 + wn * 64;
            const int krow = lane >> 2;
            const int pcol = (lane & 3) * 2;
            #pragma unroll
            for (int mf = 0; mf < 4; mf++) {
                #pragma unroll
                for (int nf = 0; nf < 8; nf++) {
                    size_t o = obase + (size_t)(mf * 16 + krow) * PLEN + nf * 8 + pcol;
                    *(float2*)(out + o)            = make_float2(acc[mf][nf][0], acc[mf][nf][1]);
                    *(float2*)(out + o + 8 * PLEN) = make_float2(acc[mf][nf][2], acc[mf][nf][3]);
                }
            }
        }
    }
}

extern "C" void kernel_launch(void* const* d_in, const int* in_sizes, int n_in,
                              void* d_out, int out_size) {
    static int nsm = 0;
    if (nsm == 0) {
        int dev = 0;
        cudaGetDevice(&dev);
        if (cudaDeviceGetAttribute(&nsm, cudaDevAttrMultiProcessorCount, dev) != cudaSuccess || nsm <= 0)
            nsm = 148;
        cudaFuncSetAttribute(markonv_kernel, cudaFuncAttributeMaxDynamicSharedMemorySize, SMEM_TOTAL);
    }
    markonv_kernel<<<nsm, NTH, SMEM_TOTAL>>>(
        (const float*)d_in[0], (const float*)d_in[1], (float*)d_out);
}

// round 9
// speedup vs baseline: 1.3685x; 1.0055x over previous
#include <cuda_runtime.h>
#include <cuda_fp16.h>
#include <cstdint>

#define NTH     256
#define PT      256
#define NPT     39
#define NTILES  (128 * NPT)
#define PLEN    9984
#define LL      10000
#define NK      128

// smem layout (bytes)
#define XS_OFF  0                 // 2 x 288 float4 (272 used) = 9216B
#define W_OFF   9216              // 64KB: W'[k=128][s=256] fp16, blocked SW128
#define P0_OFF  74752             // 2 x 13056B: P[272 rows][16 cc] fp16, 48B row stride
#define PSZ     13056
#define SMEM_TOTAL 100864

static __device__ __forceinline__ uint32_t s2u(const void* p) {
    uint32_t a;
    asm("{ .reg .u64 t; cvta.to.shared.u64 t, %1; cvt.u32.u64 %0, t; }" : "=r"(a) : "l"(p));
    return a;
}

// Blocked SW128 atom layout for W [128 rows x 256 halves]; atom = 8 rows x 128B, rstride 16.
static __device__ __forceinline__ uint32_t wa(int row, int s) {
    uint32_t byte = (uint32_t)((((row >> 3) + ((s >> 6) << 4)) << 10) + ((row & 7) << 7) + ((s & 63) << 1));
    return byte ^ ((byte >> 3) & 0x70);
}
// Unswizzled byte offset (incremental addressing adds here, then XORs the mask)
static __device__ __forceinline__ uint32_t wa_u(int row, int s) {
    return (uint32_t)((((row >> 3) + ((s >> 6) << 4)) << 10) + ((row & 7) << 7) + ((s & 63) << 1));
}

static __device__ __forceinline__ uint32_t f2h2(float a, float b) {
    __half2 h = __floats2half2_rn(a, b);
    return *reinterpret_cast<uint32_t*>(&h);
}

static __device__ __forceinline__ void ldsm4(uint32_t (&r)[4], uint32_t addr) {
    asm volatile("ldmatrix.sync.aligned.m8n8.x4.shared.b16 {%0,%1,%2,%3}, [%4];"
        : "=r"(r[0]), "=r"(r[1]), "=r"(r[2]), "=r"(r[3]) : "r"(addr));
}

static __device__ __forceinline__ void sts128(uint32_t addr, uint4 v) {
    asm volatile("st.shared.v4.b32 [%0], {%1,%2,%3,%4};"
        :: "r"(addr), "r"(v.x), "r"(v.y), "r"(v.z), "r"(v.w));
}

static __device__ __forceinline__ void mma16816(float (&d)[4], const uint32_t (&a)[4],
                                                uint32_t b0, uint32_t b1) {
    asm volatile("mma.sync.aligned.m16n8k16.row.col.f32.f16.f16.f32 "
        "{%0,%1,%2,%3}, {%4,%5,%6,%7}, {%8,%9}, {%0,%1,%2,%3};"
        : "+f"(d[0]), "+f"(d[1]), "+f"(d[2]), "+f"(d[3])
        : "r"(a[0]), "r"(a[1]), "r"(a[2]), "r"(a[3]), "r"(b0), "r"(b1));
}

// P row t: P[t][c1*4+c2] = x[t][c1] * x[t+1][c2]; 16 halves = 32B at t*48 (48B stride).
static __device__ __forceinline__ void build_p(uint32_t pbase, const float4* xs, int t) {
    const float4 a = xs[t], c = xs[t + 1];
    uint4 lo, hi;
    lo.x = f2h2(a.x * c.x, a.x * c.y); lo.y = f2h2(a.x * c.z, a.x * c.w);
    lo.z = f2h2(a.y * c.x, a.y * c.y); lo.w = f2h2(a.y * c.z, a.y * c.w);
    hi.x = f2h2(a.z * c.x, a.z * c.y); hi.y = f2h2(a.z * c.z, a.z * c.w);
    hi.z = f2h2(a.w * c.x, a.w * c.y); hi.w = f2h2(a.w * c.z, a.w * c.w);
    sts128(pbase + t * 48, lo);
    sts128(pbase + t * 48 + 16, hi);
}

static __device__ __forceinline__ const float4* xwin(const float* x, int tile) {
    const int b = tile / NPT, p0 = (tile - b * NPT) * PT;
    return (const float4*)(x + ((size_t)b * LL + p0) * 4);
}

__global__ void __launch_bounds__(NTH, 1)
markonv_kernel(const float* __restrict__ x, const float* __restrict__ ker,
               float* __restrict__ out) {
    extern __shared__ char smem[];
    uint32_t sb = s2u(smem);
    const int tid = threadIdx.x;
    const int lane = tid & 31;
    const int wid = tid >> 5;
    const int wm = wid & 1;   // warp M (k): 2 x 64 rows
    const int wn = wid >> 1;  // warp N (p): 4 x 64 cols
    const int G = gridDim.x;

    // ---- stage W once: W'[k][s] = ker[s*128 + k] ----
    for (int idx = tid; idx < 128 * 128; idx += NTH) {
        int k = idx & 127, s = (idx >> 7) << 1;
        *(uint32_t*)(smem + W_OFF + wa(k, s)) =
            f2h2(ker[s * 128 + k], ker[s * 128 + 128 + k]);
    }

    // A (W) lane addressing: unswizzled base + per-thread XOR mask (bits 4-6).
    const int a_row = wm * 64 + (lane & 15);
    const uint32_t wbyteU = wa_u(a_row, (lane >> 4) << 3);
    const uint32_t wmask  = (uint32_t)((a_row & 7) << 4);
    // B (P) lane addressing: linear; per-kstep +48, rows +16 -> +768.
    const uint32_t pblane = (uint32_t)((wn * 64 + (lane & 7) + ((lane >> 4) << 3)) * 48
                                       + (((lane >> 3) & 1) << 4));

    int tile = blockIdx.x;
    float4 xr = make_float4(0.f, 0.f, 0.f, 0.f), xrb = xr;

    // ---- prologue: stage xs[0], build P[0], prefetch x(tile+G) ----
    {
        const float4* w0 = xwin(x, tile);
        xr = w0[tid];
        if (tid < 16) xrb = w0[256 + tid];
        float4* xs0 = (float4*)(smem + XS_OFF);
        xs0[tid] = xr;
        if (tid < 16) xs0[256 + tid] = xrb;
        __syncthreads();
        build_p(sb + P0_OFF, xs0, tid);
        if (tid < 16) build_p(sb + P0_OFF, xs0, 256 + tid);
        if (tile + G < NTILES) {
            const float4* w1 = xwin(x, tile + G);
            xr = w1[tid];
            if (tid < 16) xrb = w1[256 + tid];
        }
    }

    int n = 0;
    for (; tile < NTILES; tile += G, n++) {
        const int cb = n & 1, nb = cb ^ 1;

        // publish x window for tile+G; barrier publishes P[cb] and xs[nb]
        float4* xsn = (float4*)(smem + XS_OFF) + nb * 288;
        xsn[tid] = xr;
        if (tid < 16) xsn[256 + tid] = xrb;
        __syncthreads();

        const int b = tile / NPT;
        const int p0 = (tile - b * NPT) * PT;

        // prefetch x(tile+2G)
        if (tile + 2 * G < NTILES) {
            const float4* w2 = xwin(x, tile + 2 * G);
            xr = w2[tid];
            if (tid < 16) xrb = w2[256 + tid];
        }

        // build P[nb] (tiny: 272 rows)
        {
            const uint32_t pn = sb + P0_OFF + nb * PSZ;
            build_p(pn, xsn, tid);
            if (tid < 16) build_p(pn, xsn, 256 + tid);
        }

        // ---- GEMM: D[128k x 256p] = W * V^T, V[p][16ks+cc] = P[p+ks][cc] ----
        // Software-pipelined: frags for ks+1 loaded during MMAs of ks.
        const uint32_t pcur = sb + P0_OFF + cb * PSZ + pblane;
        const uint32_t wsb  = sb + W_OFF;

        float acc[4][8][4];
        #pragma unroll
        for (int mf = 0; mf < 4; mf++)
            #pragma unroll
            for (int nf = 0; nf < 8; nf++)
                #pragma unroll
                for (int e = 0; e < 4; e++) acc[mf][nf][e] = 0.f;

        uint32_t af[2][4][4], bf[2][4][4];

        // preload kstep 0
        {
            const uint32_t ab = wsb + ((wbyteU + 0u) ^ wmask);
            const uint32_t bb = pcur;
            ldsm4(af[0][0], ab);
            ldsm4(af[0][1], ab + 2048);
            ldsm4(af[0][2], ab + 4096);
            ldsm4(af[0][3], ab + 6144);
            ldsm4(bf[0][0], bb);
            ldsm4(bf[0][1], bb + 768);
            ldsm4(bf[0][2], bb + 1536);
            ldsm4(bf[0][3], bb + 2304);
        }

        #pragma unroll
        for (int ks = 0; ks < 16; ks++) {
            const int cur = ks & 1, nxt = cur ^ 1;
            if (ks < 15) {
                const uint32_t d = (uint32_t)(((ks + 1) >> 2) * 16384 + ((ks + 1) & 3) * 32);
                const uint32_t ab = wsb + ((wbyteU + d) ^ wmask);
                const uint32_t bb = pcur + (uint32_t)((ks + 1) * 48);
                ldsm4(af[nxt][0], ab);
                ldsm4(af[nxt][1], ab + 2048);
                ldsm4(af[nxt][2], ab + 4096);
                ldsm4(af[nxt][3], ab + 6144);
                ldsm4(bf[nxt][0], bb);
                ldsm4(bf[nxt][1], bb + 768);
                ldsm4(bf[nxt][2], bb + 1536);
                ldsm4(bf[nxt][3], bb + 2304);
            }
            #pragma unroll
            for (int j = 0; j < 4; j++)
                #pragma unroll
                for (int mf = 0; mf < 4; mf++) {
                    mma16816(acc[mf][2 * j],     af[cur][mf], bf[cur][j][0], bf[cur][j][1]);
                    mma16816(acc[mf][2 * j + 1], af[cur][mf], bf[cur][j][2], bf[cur][j][3]);
                }
        }

        // ---- epilogue: direct STG.64 (rows = k, cols = consecutive p) ----
        {
            const size_t obase = ((size_t)b * NK + wm * 64) * PLEN + p0 + wn * 64;
            const int krow = lane >> 2;
            const int pcol = (lane & 3) * 2;
            #pragma unroll
            for (int mf = 0; mf < 4; mf++) {
                #pragma unroll
                for (int nf = 0; nf < 8; nf++) {
                    size_t o = obase + (size_t)(mf * 16 + krow) * PLEN + nf * 8 + pcol;
                    *(float2*)(out + o)            = make_float2(acc[mf][nf][0], acc[mf][nf][1]);
                    *(float2*)(out + o + 8 * PLEN) = make_float2(acc[mf][nf][2], acc[mf][nf][3]);
                }
            }
        }
    }
}

extern "C" void kernel_launch(void* const* d_in, const int* in_sizes, int n_in,
                              void* d_out, int out_size) {
    static int nsm = 0;
    if (nsm == 0) {
        int dev = 0;
        cudaGetDevice(&dev);
        if (cudaDeviceGetAttribute(&nsm, cudaDevAttrMultiProcessorCount, dev) != cudaSuccess || nsm <= 0)
            nsm = 148;
        cudaFuncSetAttribute(markonv_kernel, cudaFuncAttributeMaxDynamicSharedMemorySize, SMEM_TOTAL);
    }
    markonv_kernel<<<nsm, NTH, SMEM_TOTAL>>>(
        (const float*)d_in[0], (const float*)d_in[1], (float*)d_out);
}

// round 10
// speedup vs baseline: 1.4646x; 1.0702x over previous
#include <cuda_runtime.h>
#include <cuda_fp16.h>
#include <cstdint>

#define NTH     256
#define PT      128
#define NPT     78
#define NTILES  (128 * NPT)
#define PLEN    9984
#define LL      10000
#define NK      128

// smem layout (bytes)
#define XS_OFF  0                 // 2 x 160 float4 (144 used) = 5120B
#define W_OFF   5120              // 64KB: W'[k=128][s=256] fp16, blocked SW128
#define P0_OFF  70656             // 2 x 6912B: P[144 rows][16 cc] fp16, 48B row stride
#define PSZ     6912
#define SMEM_TOTAL 84480

static __device__ __forceinline__ uint32_t s2u(const void* p) {
    uint32_t a;
    asm("{ .reg .u64 t; cvta.to.shared.u64 t, %1; cvt.u32.u64 %0, t; }" : "=r"(a) : "l"(p));
    return a;
}

// Blocked SW128 atom layout for W [128 rows x 256 halves]; atom = 8 rows x 128B, rstride 16.
static __device__ __forceinline__ uint32_t wa(int row, int s) {
    uint32_t byte = (uint32_t)((((row >> 3) + ((s >> 6) << 4)) << 10) + ((row & 7) << 7) + ((s & 63) << 1));
    return byte ^ ((byte >> 3) & 0x70);
}
// Unswizzled byte offset (incremental addressing adds here, then XORs the mask)
static __device__ __forceinline__ uint32_t wa_u(int row, int s) {
    return (uint32_t)((((row >> 3) + ((s >> 6) << 4)) << 10) + ((row & 7) << 7) + ((s & 63) << 1));
}

static __device__ __forceinline__ uint32_t f2h2(float a, float b) {
    __half2 h = __floats2half2_rn(a, b);
    return *reinterpret_cast<uint32_t*>(&h);
}

static __device__ __forceinline__ void ldsm4(uint32_t (&r)[4], uint32_t addr) {
    asm volatile("ldmatrix.sync.aligned.m8n8.x4.shared.b16 {%0,%1,%2,%3}, [%4];"
        : "=r"(r[0]), "=r"(r[1]), "=r"(r[2]), "=r"(r[3]) : "r"(addr));
}

static __device__ __forceinline__ void sts128(uint32_t addr, uint4 v) {
    asm volatile("st.shared.v4.b32 [%0], {%1,%2,%3,%4};"
        :: "r"(addr), "r"(v.x), "r"(v.y), "r"(v.z), "r"(v.w));
}

static __device__ __forceinline__ void mma16816(float (&d)[4], const uint32_t (&a)[4],
                                                uint32_t b0, uint32_t b1) {
    asm volatile("mma.sync.aligned.m16n8k16.row.col.f32.f16.f16.f32 "
        "{%0,%1,%2,%3}, {%4,%5,%6,%7}, {%8,%9}, {%0,%1,%2,%3};"
        : "+f"(d[0]), "+f"(d[1]), "+f"(d[2]), "+f"(d[3])
        : "r"(a[0]), "r"(a[1]), "r"(a[2]), "r"(a[3]), "r"(b0), "r"(b1));
}

// P row t: P[t][c1*4+c2] = x[t][c1] * x[t+1][c2]; 16 halves = 32B at t*48 (48B stride).
static __device__ __forceinline__ void build_p(uint32_t pbase, const float4* xs, int t) {
    const float4 a = xs[t], c = xs[t + 1];
    uint4 lo, hi;
    lo.x = f2h2(a.x * c.x, a.x * c.y); lo.y = f2h2(a.x * c.z, a.x * c.w);
    lo.z = f2h2(a.y * c.x, a.y * c.y); lo.w = f2h2(a.y * c.z, a.y * c.w);
    hi.x = f2h2(a.z * c.x, a.z * c.y); hi.y = f2h2(a.z * c.z, a.z * c.w);
    hi.z = f2h2(a.w * c.x, a.w * c.y); hi.w = f2h2(a.w * c.z, a.w * c.w);
    sts128(pbase + t * 48, lo);
    sts128(pbase + t * 48 + 16, hi);
}

static __device__ __forceinline__ const float4* xwin(const float* x, int tile) {
    const int b = tile / NPT, p0 = (tile - b * NPT) * PT;
    return (const float4*)(x + ((size_t)b * LL + p0) * 4);
}

__global__ void __launch_bounds__(NTH, 2)
markonv_kernel(const float* __restrict__ x, const float* __restrict__ ker,
               float* __restrict__ out) {
    extern __shared__ char smem[];
    uint32_t sb = s2u(smem);
    const int tid = threadIdx.x;
    const int lane = tid & 31;
    const int wid = tid >> 5;
    const int wm = wid & 1;   // warp M (k): 2 x 64 rows
    const int wn = wid >> 1;  // warp N (p): 4 x 32 cols
    const int G = gridDim.x;

    // ---- stage W once per CTA: W'[k][s] = ker[s*128 + k] ----
    for (int idx = tid; idx < 128 * 128; idx += NTH) {
        int k = idx & 127, s = (idx >> 7) << 1;
        *(uint32_t*)(smem + W_OFF + wa(k, s)) =
            f2h2(ker[s * 128 + k], ker[s * 128 + 128 + k]);
    }

    // A (W) lane addressing: unswizzled base + per-thread XOR mask (bits 4-6).
    const int a_row = wm * 64 + (lane & 15);
    const uint32_t wbyteU = wa_u(a_row, (lane >> 4) << 3);
    const uint32_t wmask  = (uint32_t)((a_row & 7) << 4);
    // B (P) lane addressing: linear; per-kstep +48, rows +16 -> +768.
    const uint32_t pblane = (uint32_t)((wn * 32 + (lane & 7) + ((lane >> 4) << 3)) * 48
                                       + (((lane >> 3) & 1) << 4));

    int tile = blockIdx.x;
    float4 xr = make_float4(0.f, 0.f, 0.f, 0.f);

    // ---- prologue: stage xs[0], build P[0], prefetch x(tile+G) ----
    {
        if (tid < 144) {
            xr = xwin(x, tile)[tid];
            ((float4*)(smem + XS_OFF))[tid] = xr;
        }
        __syncthreads();
        if (tid < 144) build_p(sb + P0_OFF, (const float4*)(smem + XS_OFF), tid);
        if (tid < 144 && tile + G < NTILES) xr = xwin(x, tile + G)[tid];
    }

    int n = 0;
    for (; tile < NTILES; tile += G, n++) {
        const int cb = n & 1, nb = cb ^ 1;

        // publish x window for tile+G; barrier publishes P[cb] and xs[nb]
        float4* xsn = (float4*)(smem + XS_OFF) + nb * 160;
        if (tid < 144) xsn[tid] = xr;
        __syncthreads();

        const int b = tile / NPT;
        const int p0 = (tile - b * NPT) * PT;

        // prefetch x(tile+2G)
        if (tid < 144 && tile + 2 * G < NTILES) xr = xwin(x, tile + 2 * G)[tid];

        // build P[nb] (tiny: 144 rows)
        if (tid < 144) build_p(sb + P0_OFF + nb * PSZ, xsn, tid);

        // ---- GEMM: D[128k x 128p] = W * V^T, V[p][16ks+cc] = P[p+ks][cc] ----
        const uint32_t pcur = sb + P0_OFF + cb * PSZ + pblane;
        const uint32_t wsb  = sb + W_OFF;

        float acc[4][4][4];
        #pragma unroll
        for (int mf = 0; mf < 4; mf++)
            #pragma unroll
            for (int nf = 0; nf < 4; nf++)
                #pragma unroll
                for (int e = 0; e < 4; e++) acc[mf][nf][e] = 0.f;

        #pragma unroll
        for (int ks = 0; ks < 16; ks++) {
            uint32_t af[4][4], bf[2][4];
            const uint32_t d = (uint32_t)((ks >> 2) * 16384 + (ks & 3) * 32);
            const uint32_t ab = wsb + ((wbyteU + d) ^ wmask);
            const uint32_t bb = pcur + (uint32_t)(ks * 48);
            ldsm4(af[0], ab);
            ldsm4(af[1], ab + 2048);
            ldsm4(af[2], ab + 4096);
            ldsm4(af[3], ab + 6144);
            ldsm4(bf[0], bb);
            ldsm4(bf[1], bb + 768);
            #pragma unroll
            for (int mf = 0; mf < 4; mf++) {
                mma16816(acc[mf][0], af[mf], bf[0][0], bf[0][1]);
                mma16816(acc[mf][1], af[mf], bf[0][2], bf[0][3]);
                mma16816(acc[mf][2], af[mf], bf[1][0], bf[1][1]);
                mma16816(acc[mf][3], af[mf], bf[1][2], bf[1][3]);
            }
        }

        // ---- epilogue: direct STG.64 (rows = k, cols = consecutive p) ----
        {
            const size_t obase = ((size_t)b * NK + wm * 64) * PLEN + p0 + wn * 32;
            const int krow = lane >> 2;
            const int pcol = (lane & 3) * 2;
            #pragma unroll
            for (int mf = 0; mf < 4; mf++) {
                #pragma unroll
                for (int nf = 0; nf < 4; nf++) {
                    size_t o = obase + (size_t)(mf * 16 + krow) * PLEN + nf * 8 + pcol;
                    *(float2*)(out + o)            = make_float2(acc[mf][nf][0], acc[mf][nf][1]);
                    *(float2*)(out + o + 8 * PLEN) = make_float2(acc[mf][nf][2], acc[mf][nf][3]);
                }
            }
        }
    }
}

extern "C" void kernel_launch(void* const* d_in, const int* in_sizes, int n_in,
                              void* d_out, int out_size) {
    static int nsm = 0;
    if (nsm == 0) {
        int dev = 0;
        cudaGetDevice(&dev);
        if (cudaDeviceGetAttribute(&nsm, cudaDevAttrMultiProcessorCount, dev) != cudaSuccess || nsm <= 0)
            nsm = 148;
        cudaFuncSetAttribute(markonv_kernel, cudaFuncAttributeMaxDynamicSharedMemorySize, SMEM_TOTAL);
    }
    markonv_kernel<<<2 * nsm, NTH, SMEM_TOTAL>>>(
        (const float*)d_in[0], (const float*)d_in[1], (float*)d_out);
}